// round 1
// baseline (speedup 1.0000x reference)
#include <cuda_runtime.h>
#include <cstdint>

#define NTHREADS 256
#define TILE_M   128
#define SW1      136   // W1 smem row stride (floats): 136%32==8 -> conflict-free B frags
#define SW2      264   // W2 smem row stride: 264%32==8 -> conflict-free B frags
#define SH       132   // H/A smem row stride: 132%32==4 -> conflict-free A frags
#define RAW_OFF  84    // raw pose staged in H region cols 84..128

// smem float offsets
#define OFF_W2 0
#define OFF_W1 (128 * SW2)              // 33792
#define OFF_H  (OFF_W1 + 48 * SW1)      // 40320
#define OFF_PS (OFF_H + 128 * SH)       // 57216
#define SMEM_FLOATS (OFF_PS + 512)      // 57728
#define SMEM_BYTES  (SMEM_FLOATS * 4)   // 230912

__device__ __forceinline__ float tf32r(float x) {
    uint32_t u;
    asm("cvt.rna.tf32.f32 %0, %1;" : "=r"(u) : "f"(x));
    return __uint_as_float(u);
}

__device__ __forceinline__ float gelu_exact(float x) {
    return 0.5f * x * (1.0f + erff(x * 0.7071067811865476f));
}

#define MMA_TF32(C, A, B0, B1)                                               \
    asm volatile("mma.sync.aligned.m16n8k8.row.col.f32.tf32.tf32.f32 "       \
                 "{%0,%1,%2,%3}, {%4,%5,%6,%7}, {%8,%9}, {%0,%1,%2,%3};"     \
                 : "+f"(C[0]), "+f"(C[1]), "+f"(C[2]), "+f"(C[3])            \
                 : "r"(A[0]), "r"(A[1]), "r"(A[2]), "r"(A[3]),               \
                   "r"(B0), "r"(B1))

__global__ void __launch_bounds__(NTHREADS, 1)
pose_mlp_kernel(const float* __restrict__ pose,
                const float* __restrict__ ln1g, const float* __restrict__ ln1b,
                const float* __restrict__ w1,   const float* __restrict__ b1,
                const float* __restrict__ w2,   const float* __restrict__ b2,
                const float* __restrict__ ln2g, const float* __restrict__ ln2b,
                float* __restrict__ out, int ntiles)
{
    extern __shared__ float smem[];
    float*  W2s = smem + OFF_W2;
    float*  W1s = smem + OFF_W1;
    float*  Hs  = smem + OFF_H;
    float2* PS  = (float2*)(smem + OFF_PS);

    const int tid  = threadIdx.x;
    const int lane = tid & 31;
    const int warp = tid >> 5;
    const int g    = lane >> 2;   // groupID
    const int t    = lane & 3;    // threadID_in_group
    const int wr   = warp >> 1;   // warp row: rows [wr*32, wr*32+32)
    const int wc   = warp & 1;    // warp col half

    // ---- one-time: weights -> smem as tf32 ----
    for (int i = tid; i < 8192; i += NTHREADS) {           // W2: 128x256 via float4
        int k = i >> 6;
        int c = (i & 63) << 2;
        float4 v = reinterpret_cast<const float4*>(w2)[i];
        float* d = &W2s[k * SW2 + c];
        d[0] = tf32r(v.x); d[1] = tf32r(v.y); d[2] = tf32r(v.z); d[3] = tf32r(v.w);
    }
    for (int i = tid; i < 48 * 128; i += NTHREADS) {       // W1: 45x128 zero-padded to 48
        int k = i >> 7;
        int c = i & 127;
        W1s[k * SW1 + c] = (k < 45) ? tf32r(w1[k * 128 + c]) : 0.0f;
    }

    const float* Abase = &Hs[(wr * 32 + g) * SH + t];

    for (int tile = blockIdx.x; tile < ntiles; tile += gridDim.x) {
        __syncthreads();   // Hs free (prev GEMM2 done) + first-iter weight fill visible

        // ---- stage pose tile (coalesced) into Hs cols [RAW_OFF, RAW_OFF+45) ----
        const float* src = pose + (size_t)tile * (TILE_M * 45);
        for (int i = tid; i < TILE_M * 45; i += NTHREADS) {
            int r = i / 45;
            int c = i - r * 45;
            Hs[r * SH + RAW_OFF + c] = src[i];
        }
        __syncthreads();

        // ---- LN1: one thread per row -> tf32 A-tile in Hs cols 0..47 ----
        if (tid < TILE_M) {
            float x[45];
            float s = 0.f;
            #pragma unroll
            for (int c = 0; c < 45; c++) { x[c] = Hs[tid * SH + RAW_OFF + c]; s += x[c]; }
            float mu = s * (1.0f / 45.0f);
            float v = 0.f;
            #pragma unroll
            for (int c = 0; c < 45; c++) { float d = x[c] - mu; v += d * d; }
            float rstd = rsqrtf(v * (1.0f / 45.0f) + 1e-5f);
            #pragma unroll
            for (int c = 0; c < 45; c++) {
                float y = (x[c] - mu) * rstd * ln1g[c] + ln1b[c];
                Hs[tid * SH + c] = tf32r(y);
            }
            Hs[tid * SH + 45] = 0.f; Hs[tid * SH + 46] = 0.f; Hs[tid * SH + 47] = 0.f;
        }
        __syncthreads();

        // ---- GEMM1: [128x48] x [48x128] -> acc1, bias folded into init ----
        float acc1[2][8][4];
        #pragma unroll
        for (int n = 0; n < 8; n++) {
            float2 bv = *reinterpret_cast<const float2*>(&b1[wc * 64 + n * 8 + 2 * t]);
            #pragma unroll
            for (int mi = 0; mi < 2; mi++) {
                acc1[mi][n][0] = bv.x; acc1[mi][n][1] = bv.y;
                acc1[mi][n][2] = bv.x; acc1[mi][n][3] = bv.y;
            }
        }
        {
            const float* Bb1 = &W1s[t * SW1 + wc * 64 + g];
            #pragma unroll
            for (int kk = 0; kk < 6; kk++) {
                uint32_t a[2][4];
                #pragma unroll
                for (int mi = 0; mi < 2; mi++) {
                    const float* ap = Abase + mi * 16 * SH + kk * 8;
                    a[mi][0] = __float_as_uint(ap[0]);
                    a[mi][1] = __float_as_uint(ap[8 * SH]);
                    a[mi][2] = __float_as_uint(ap[4]);
                    a[mi][3] = __float_as_uint(ap[8 * SH + 4]);
                }
                const float* bk = Bb1 + kk * 8 * SW1;
                #pragma unroll
                for (int n = 0; n < 8; n++) {
                    uint32_t b0v = __float_as_uint(bk[n * 8]);
                    uint32_t b1v = __float_as_uint(bk[4 * SW1 + n * 8]);
                    MMA_TF32(acc1[0][n], a[0], b0v, b1v);
                    MMA_TF32(acc1[1][n], a[1], b0v, b1v);
                }
            }
        }
        __syncthreads();   // all A-tile reads done before H overwrites cols 0..127

        // ---- epilogue1: GELU -> H (tf32) in Hs cols 0..127 ----
        #pragma unroll
        for (int mi = 0; mi < 2; mi++) {
            int rb = wr * 32 + mi * 16 + g;
            #pragma unroll
            for (int n = 0; n < 8; n++) {
                int c = wc * 64 + n * 8 + 2 * t;
                float2 v0, v1;
                v0.x = tf32r(gelu_exact(acc1[mi][n][0]));
                v0.y = tf32r(gelu_exact(acc1[mi][n][1]));
                v1.x = tf32r(gelu_exact(acc1[mi][n][2]));
                v1.y = tf32r(gelu_exact(acc1[mi][n][3]));
                *reinterpret_cast<float2*>(&Hs[rb * SH + c])       = v0;
                *reinterpret_cast<float2*>(&Hs[(rb + 8) * SH + c]) = v1;
            }
        }
        __syncthreads();

        // ---- GEMM2: [128x128] x [128x256] -> acc2, b2 folded into init ----
        float acc2[2][16][4];
        #pragma unroll
        for (int n = 0; n < 16; n++) {
            float2 bv = *reinterpret_cast<const float2*>(&b2[wc * 128 + n * 8 + 2 * t]);
            #pragma unroll
            for (int mi = 0; mi < 2; mi++) {
                acc2[mi][n][0] = bv.x; acc2[mi][n][1] = bv.y;
                acc2[mi][n][2] = bv.x; acc2[mi][n][3] = bv.y;
            }
        }
        {
            const float* Bb2 = &W2s[t * SW2 + wc * 128 + g];
            #pragma unroll 2
            for (int kk = 0; kk < 16; kk++) {
                uint32_t a[2][4];
                #pragma unroll
                for (int mi = 0; mi < 2; mi++) {
                    const float* ap = Abase + mi * 16 * SH + kk * 8;
                    a[mi][0] = __float_as_uint(ap[0]);
                    a[mi][1] = __float_as_uint(ap[8 * SH]);
                    a[mi][2] = __float_as_uint(ap[4]);
                    a[mi][3] = __float_as_uint(ap[8 * SH + 4]);
                }
                const float* bk = Bb2 + kk * 8 * SW2;
                #pragma unroll
                for (int n = 0; n < 16; n++) {
                    uint32_t b0v = __float_as_uint(bk[n * 8]);
                    uint32_t b1v = __float_as_uint(bk[4 * SW2 + n * 8]);
                    MMA_TF32(acc2[0][n], a[0], b0v, b1v);
                    MMA_TF32(acc2[1][n], a[1], b0v, b1v);
                }
            }
        }

        // ---- LN2 partial sums: reduce over t (4 lanes own a row-half), stash per warp-col ----
        #pragma unroll
        for (int mi = 0; mi < 2; mi++) {
            int rb = wr * 32 + mi * 16 + g;
            float s0 = 0.f, q0 = 0.f, s1 = 0.f, q1 = 0.f;
            #pragma unroll
            for (int n = 0; n < 16; n++) {
                float a0 = acc2[mi][n][0], a1 = acc2[mi][n][1];
                float a2 = acc2[mi][n][2], a3 = acc2[mi][n][3];
                s0 += a0 + a1; q0 += a0 * a0 + a1 * a1;
                s1 += a2 + a3; q1 += a2 * a2 + a3 * a3;
            }
            #pragma unroll
            for (int off = 1; off <= 2; off <<= 1) {
                s0 += __shfl_xor_sync(0xffffffffu, s0, off);
                q0 += __shfl_xor_sync(0xffffffffu, q0, off);
                s1 += __shfl_xor_sync(0xffffffffu, s1, off);
                q1 += __shfl_xor_sync(0xffffffffu, q1, off);
            }
            if (t == 0) {
                PS[rb * 2 + wc]       = make_float2(s0, q0);
                PS[(rb + 8) * 2 + wc] = make_float2(s1, q1);
            }
        }
        __syncthreads();

        // ---- epilogue2: finalize LN2, coalesced float2 stores ----
        float* outp = out + (size_t)tile * TILE_M * 256;
        #pragma unroll
        for (int mi = 0; mi < 2; mi++) {
            int rb = wr * 32 + mi * 16 + g;
            #pragma unroll
            for (int h = 0; h < 2; h++) {
                int r = rb + h * 8;
                float2 pa = PS[r * 2 + 0];
                float2 pb = PS[r * 2 + 1];
                float mu   = (pa.x + pb.x) * (1.0f / 256.0f);
                float var  = (pa.y + pb.y) * (1.0f / 256.0f) - mu * mu;
                float rstd = rsqrtf(var + 1e-5f);
                #pragma unroll
                for (int n = 0; n < 16; n++) {
                    int c = wc * 128 + n * 8 + 2 * t;
                    float2 gv = *reinterpret_cast<const float2*>(&ln2g[c]);
                    float2 bv = *reinterpret_cast<const float2*>(&ln2b[c]);
                    float v0 = acc2[mi][n][h * 2 + 0];
                    float v1 = acc2[mi][n][h * 2 + 1];
                    float2 o;
                    o.x = (v0 - mu) * rstd * gv.x + bv.x;
                    o.y = (v1 - mu) * rstd * gv.y + bv.y;
                    *reinterpret_cast<float2*>(&outp[(size_t)r * 256 + c]) = o;
                }
            }
        }
    }
}

extern "C" void kernel_launch(void* const* d_in, const int* in_sizes, int n_in,
                              void* d_out, int out_size)
{
    const float* pose = (const float*)d_in[0];
    const float* ln1g = (const float*)d_in[1];
    const float* ln1b = (const float*)d_in[2];
    const float* w1   = (const float*)d_in[3];
    const float* b1   = (const float*)d_in[4];
    const float* w2   = (const float*)d_in[5];
    const float* b2   = (const float*)d_in[6];
    const float* ln2g = (const float*)d_in[7];
    const float* ln2b = (const float*)d_in[8];
    float* out = (float*)d_out;

    int nrows  = in_sizes[0] / 45;
    int ntiles = nrows / TILE_M;

    int dev = 0;
    cudaGetDevice(&dev);
    int nsm = 148;
    cudaDeviceGetAttribute(&nsm, cudaDevAttrMultiProcessorCount, dev);

    cudaFuncSetAttribute(pose_mlp_kernel,
                         cudaFuncAttributeMaxDynamicSharedMemorySize, SMEM_BYTES);

    int grid = nsm < ntiles ? nsm : ntiles;
    pose_mlp_kernel<<<grid, NTHREADS, SMEM_BYTES>>>(
        pose, ln1g, ln1b, w1, b1, w2, b2, ln2g, ln2b, out, ntiles);
}

// round 2
// speedup vs baseline: 1.4880x; 1.4880x over previous
#include <cuda_runtime.h>
#include <cuda_fp16.h>
#include <cstdint>

#define NTHREADS 512
#define TILE_M   128

// half-element strides (chosen for conflict-free ldmatrix / stores)
#define SW2 264   // W2h [128][256]
#define SW1 136   // W1h [48][128]
#define SA   56   // A1h [128][48]
#define SHH 136   // Hh  [128][128]

// smem byte offsets
#define OFF_W2   0
#define OFF_W1   67584                  // 128*264*2
#define OFF_A1   80640                  // +48*136*2
#define OFF_H    94976                  // +128*56*2
#define OFF_ST   129792                 // +128*136*2
#define OFF_PS   152832                 // +5760*4
#define OFF_LNC  156928                 // +128*4*8
#define SMEM_BYTES 157312               // +96*4

__device__ __forceinline__ unsigned su32(const void* p) {
    return (unsigned)__cvta_generic_to_shared(p);
}

__device__ __forceinline__ float gelu_exact(float x) {
    return 0.5f * x * (1.0f + erff(x * 0.7071067811865476f));
}

#define LDM_X4(R, addr)                                                        \
    asm volatile("ldmatrix.sync.aligned.m8n8.x4.shared.b16 {%0,%1,%2,%3}, [%4];" \
        : "=r"((R)[0]), "=r"((R)[1]), "=r"((R)[2]), "=r"((R)[3]) : "r"(addr))

#define LDM_X4T(R, addr)                                                       \
    asm volatile("ldmatrix.sync.aligned.m8n8.x4.trans.shared.b16 {%0,%1,%2,%3}, [%4];" \
        : "=r"((R)[0]), "=r"((R)[1]), "=r"((R)[2]), "=r"((R)[3]) : "r"(addr))

#define MMA_F16(C, A, b0, b1)                                                  \
    asm volatile("mma.sync.aligned.m16n8k16.row.col.f32.f16.f16.f32 "          \
        "{%0,%1,%2,%3}, {%4,%5,%6,%7}, {%8,%9}, {%0,%1,%2,%3};"                \
        : "+f"((C)[0]), "+f"((C)[1]), "+f"((C)[2]), "+f"((C)[3])               \
        : "r"((A)[0]), "r"((A)[1]), "r"((A)[2]), "r"((A)[3]), "r"(b0), "r"(b1))

__global__ void __launch_bounds__(NTHREADS, 1)
pose_mlp_kernel(const float* __restrict__ pose,
                const float* __restrict__ ln1g, const float* __restrict__ ln1b,
                const float* __restrict__ w1,   const float* __restrict__ b1,
                const float* __restrict__ w2,   const float* __restrict__ b2,
                const float* __restrict__ ln2g, const float* __restrict__ ln2b,
                float* __restrict__ out, int ntiles)
{
    extern __shared__ char smem[];
    __half* W2h = (__half*)(smem + OFF_W2);
    __half* W1h = (__half*)(smem + OFF_W1);
    __half* A1h = (__half*)(smem + OFF_A1);
    __half* Hh  = (__half*)(smem + OFF_H);
    float*  ST  = (float*)(smem + OFF_ST);
    float2* PS  = (float2*)(smem + OFF_PS);
    float*  LNC = (float*)(smem + OFF_LNC);

    const int tid  = threadIdx.x;
    const int lane = tid & 31;
    const int warp = tid >> 5;
    const int g    = lane >> 2;   // groupID
    const int t    = lane & 3;    // threadID in group
    const int wr   = warp >> 2;   // warp row: rows [wr*32, wr*32+32)
    const int wc   = warp & 3;    // warp col quarter

    // ldmatrix lane-address offsets
    const int lm_m  = lane >> 3;              // matrix 0..3
    const int lm_r  = lane & 7;               // row within matrix
    const int a_row = lm_r + (lm_m & 1) * 8;  // A: m1,m3 -> rows +8
    const int a_kof = (lm_m >> 1) * 8;        // A: m2,m3 -> k +8
    const int b_kof = lm_r + (lm_m & 1) * 8;  // B: m1,m3 -> k rows +8
    const int b_cof = (lm_m >> 1) * 8;        // B: m2,m3 -> cols +8

    // ---- one-time: weights -> smem as fp16 ----
    for (int i = tid; i < 8192; i += NTHREADS) {            // W2: 128x256 via float4
        int k = i >> 6;
        int c = (i & 63) << 2;
        float4 v = reinterpret_cast<const float4*>(w2)[i];
        __half2* d = (__half2*)&W2h[k * SW2 + c];
        d[0] = __floats2half2_rn(v.x, v.y);
        d[1] = __floats2half2_rn(v.z, v.w);
    }
    for (int i = tid; i < 48 * 128; i += NTHREADS) {        // W1: 45x128, rows 45..47 zero
        int k = i >> 7;
        int c = i & 127;
        W1h[k * SW1 + c] = (k < 45) ? __float2half_rn(w1[k * 128 + c])
                                    : __float2half_rn(0.0f);
    }
    if (tid < 45) { LNC[tid] = ln1g[tid]; LNC[48 + tid] = ln1b[tid]; }

    for (int tile = blockIdx.x; tile < ntiles; tile += gridDim.x) {
        __syncthreads();   // prior-tile consumers done; weight fill visible on iter 0

        // ---- stage pose tile (coalesced copy) ----
        const float* src = pose + (size_t)tile * (TILE_M * 45);
        #pragma unroll
        for (int it = 0; it < 12; it++) {
            int i = tid + it * NTHREADS;
            if (i < TILE_M * 45) ST[i] = src[i];
        }
        __syncthreads();

        // ---- LN1: one thread per row, two-pass, write fp16 A-tile ----
        if (tid < TILE_M) {
            const float* row = &ST[tid * 45];
            float s = 0.f, q = 0.f;
            #pragma unroll
            for (int c = 0; c < 45; c++) { float x = row[c]; s += x; q += x * x; }
            float mu   = s * (1.0f / 45.0f);
            float var  = q * (1.0f / 45.0f) - mu * mu;
            float rstd = rsqrtf(fmaxf(var, 0.f) + 1e-5f);
            __half2* dst = (__half2*)&A1h[tid * SA];
            #pragma unroll
            for (int c2 = 0; c2 < 22; c2++) {
                int c = 2 * c2;
                float y0 = (row[c]     - mu) * rstd * LNC[c]     + LNC[48 + c];
                float y1 = (row[c + 1] - mu) * rstd * LNC[c + 1] + LNC[48 + c + 1];
                dst[c2] = __floats2half2_rn(y0, y1);
            }
            float y44 = (row[44] - mu) * rstd * LNC[44] + LNC[48 + 44];
            dst[22] = __floats2half2_rn(y44, 0.f);
            dst[23] = __floats2half2_rn(0.f, 0.f);
        }
        __syncthreads();

        // ---- GEMM1: [128x48] x [48x128] -> acc1 (bias folded) ----
        float acc1[2][4][4];
        #pragma unroll
        for (int n = 0; n < 4; n++) {
            float2 bv = *reinterpret_cast<const float2*>(&b1[wc * 32 + n * 8 + 2 * t]);
            #pragma unroll
            for (int mi = 0; mi < 2; mi++) {
                acc1[mi][n][0] = bv.x; acc1[mi][n][1] = bv.y;
                acc1[mi][n][2] = bv.x; acc1[mi][n][3] = bv.y;
            }
        }
        {
            unsigned ab = su32(A1h) + ((wr * 32 + a_row) * SA + a_kof) * 2;
            unsigned bb = su32(W1h) + (b_kof * SW1 + wc * 32 + b_cof) * 2;
            #pragma unroll
            for (int kk = 0; kk < 3; kk++) {
                unsigned a[2][4], b[2][4];
                LDM_X4(a[0], ab + (kk * 16) * 2);
                LDM_X4(a[1], ab + (16 * SA + kk * 16) * 2);
                LDM_X4T(b[0], bb + (kk * 16 * SW1) * 2);
                LDM_X4T(b[1], bb + (kk * 16 * SW1 + 16) * 2);
                #pragma unroll
                for (int n = 0; n < 4; n++) {
                    int p = n >> 1, qf = (n & 1) * 2;
                    MMA_F16(acc1[0][n], a[0], b[p][qf], b[p][qf + 1]);
                    MMA_F16(acc1[1][n], a[1], b[p][qf], b[p][qf + 1]);
                }
            }
        }

        // ---- epilogue1: exact-erf GELU -> fp16 H tile ----
        #pragma unroll
        for (int mi = 0; mi < 2; mi++) {
            int r = wr * 32 + mi * 16 + g;
            #pragma unroll
            for (int n = 0; n < 4; n++) {
                int c = wc * 32 + n * 8 + 2 * t;
                *(__half2*)&Hh[r * SHH + c] =
                    __floats2half2_rn(gelu_exact(acc1[mi][n][0]), gelu_exact(acc1[mi][n][1]));
                *(__half2*)&Hh[(r + 8) * SHH + c] =
                    __floats2half2_rn(gelu_exact(acc1[mi][n][2]), gelu_exact(acc1[mi][n][3]));
            }
        }
        __syncthreads();

        // ---- GEMM2: [128x128] x [128x256] -> acc2 (bias folded) ----
        float acc2[2][8][4];
        #pragma unroll
        for (int n = 0; n < 8; n++) {
            float2 bv = *reinterpret_cast<const float2*>(&b2[wc * 64 + n * 8 + 2 * t]);
            #pragma unroll
            for (int mi = 0; mi < 2; mi++) {
                acc2[mi][n][0] = bv.x; acc2[mi][n][1] = bv.y;
                acc2[mi][n][2] = bv.x; acc2[mi][n][3] = bv.y;
            }
        }
        {
            unsigned ab = su32(Hh)  + ((wr * 32 + a_row) * SHH + a_kof) * 2;
            unsigned bb = su32(W2h) + (b_kof * SW2 + wc * 64 + b_cof) * 2;
            #pragma unroll 2
            for (int kk = 0; kk < 8; kk++) {
                unsigned a[2][4], b[4][4];
                LDM_X4(a[0], ab + (kk * 16) * 2);
                LDM_X4(a[1], ab + (16 * SHH + kk * 16) * 2);
                #pragma unroll
                for (int p = 0; p < 4; p++)
                    LDM_X4T(b[p], bb + (kk * 16 * SW2 + p * 16) * 2);
                #pragma unroll
                for (int n = 0; n < 8; n++) {
                    int p = n >> 1, qf = (n & 1) * 2;
                    MMA_F16(acc2[0][n], a[0], b[p][qf], b[p][qf + 1]);
                    MMA_F16(acc2[1][n], a[1], b[p][qf], b[p][qf + 1]);
                }
            }
        }

        // ---- LN2 partial sums (reduce over t, stash per warp-col) ----
        #pragma unroll
        for (int mi = 0; mi < 2; mi++) {
            float s0 = 0.f, q0 = 0.f, s1 = 0.f, q1 = 0.f;
            #pragma unroll
            for (int n = 0; n < 8; n++) {
                float a0 = acc2[mi][n][0], a1 = acc2[mi][n][1];
                float a2 = acc2[mi][n][2], a3 = acc2[mi][n][3];
                s0 += a0 + a1; q0 += a0 * a0 + a1 * a1;
                s1 += a2 + a3; q1 += a2 * a2 + a3 * a3;
            }
            #pragma unroll
            for (int off = 1; off <= 2; off <<= 1) {
                s0 += __shfl_xor_sync(0xffffffffu, s0, off);
                q0 += __shfl_xor_sync(0xffffffffu, q0, off);
                s1 += __shfl_xor_sync(0xffffffffu, s1, off);
                q1 += __shfl_xor_sync(0xffffffffu, q1, off);
            }
            if (t == 0) {
                int r = wr * 32 + mi * 16 + g;
                PS[r * 4 + wc]       = make_float2(s0, q0);
                PS[(r + 8) * 4 + wc] = make_float2(s1, q1);
            }
        }
        __syncthreads();

        // ---- epilogue2: finalize LN2, coalesced float2 stores ----
        float* outp = out + (size_t)tile * TILE_M * 256;
        #pragma unroll
        for (int mi = 0; mi < 2; mi++) {
            #pragma unroll
            for (int h = 0; h < 2; h++) {
                int r = wr * 32 + mi * 16 + g + h * 8;
                float2 p0 = PS[r * 4 + 0], p1 = PS[r * 4 + 1];
                float2 p2 = PS[r * 4 + 2], p3 = PS[r * 4 + 3];
                float s = p0.x + p1.x + p2.x + p3.x;
                float q = p0.y + p1.y + p2.y + p3.y;
                float mu   = s * (1.0f / 256.0f);
                float var  = q * (1.0f / 256.0f) - mu * mu;
                float rstd = rsqrtf(fmaxf(var, 0.f) + 1e-5f);
                #pragma unroll
                for (int n = 0; n < 8; n++) {
                    int c = wc * 64 + n * 8 + 2 * t;
                    float2 gv = *reinterpret_cast<const float2*>(&ln2g[c]);
                    float2 bv = *reinterpret_cast<const float2*>(&ln2b[c]);
                    float v0 = acc2[mi][n][h * 2 + 0];
                    float v1 = acc2[mi][n][h * 2 + 1];
                    float2 o;
                    o.x = (v0 - mu) * rstd * gv.x + bv.x;
                    o.y = (v1 - mu) * rstd * gv.y + bv.y;
                    *reinterpret_cast<float2*>(&outp[(size_t)r * 256 + c]) = o;
                }
            }
        }
    }
}

extern "C" void kernel_launch(void* const* d_in, const int* in_sizes, int n_in,
                              void* d_out, int out_size)
{
    const float* pose = (const float*)d_in[0];
    const float* ln1g = (const float*)d_in[1];
    const float* ln1b = (const float*)d_in[2];
    const float* w1   = (const float*)d_in[3];
    const float* b1   = (const float*)d_in[4];
    const float* w2   = (const float*)d_in[5];
    const float* b2   = (const float*)d_in[6];
    const float* ln2g = (const float*)d_in[7];
    const float* ln2b = (const float*)d_in[8];
    float* out = (float*)d_out;

    int nrows  = in_sizes[0] / 45;
    int ntiles = nrows / TILE_M;

    int dev = 0;
    cudaGetDevice(&dev);
    int nsm = 148;
    cudaDeviceGetAttribute(&nsm, cudaDevAttrMultiProcessorCount, dev);

    cudaFuncSetAttribute(pose_mlp_kernel,
                         cudaFuncAttributeMaxDynamicSharedMemorySize, SMEM_BYTES);

    int grid = nsm < ntiles ? nsm : ntiles;
    pose_mlp_kernel<<<grid, NTHREADS, SMEM_BYTES>>>(
        pose, ln1g, ln1b, w1, b1, w2, b2, ln2g, ln2b, out, ntiles);
}

// round 3
// speedup vs baseline: 1.6097x; 1.0818x over previous
#include <cuda_runtime.h>
#include <cuda_fp16.h>
#include <cstdint>

#define NTHREADS 512
#define TILE_M   128

// half-element strides (conflict-free ldmatrix / stores)
#define SW2 264   // W2h [128][256]
#define SW1 136   // W1h [48][128]
#define SA   56   // A1h [128][48]
#define SHH 136   // Hh  [128][128]

// smem byte offsets
#define OFF_W2   0
#define OFF_W1   67584                  // +128*264*2
#define OFF_A1   80640                  // +48*136*2
#define OFF_H    94976                  // +128*56*2
#define OFF_ST   129792                 // +128*136*2
#define OFF_PS   175872                 // +2*5760*4 (double-buffered stage)
#define OFF_LNC  179968                 // +128*4*8
#define SMEM_BYTES 180352               // +96*4

__device__ __forceinline__ unsigned su32(const void* p) {
    return (unsigned)__cvta_generic_to_shared(p);
}

__device__ __forceinline__ float gelu_exact(float x) {
    return 0.5f * x * (1.0f + erff(x * 0.7071067811865476f));
}

#define LDM_X4(R, addr)                                                        \
    asm volatile("ldmatrix.sync.aligned.m8n8.x4.shared.b16 {%0,%1,%2,%3}, [%4];" \
        : "=r"((R)[0]), "=r"((R)[1]), "=r"((R)[2]), "=r"((R)[3]) : "r"(addr))

#define LDM_X4T(R, addr)                                                       \
    asm volatile("ldmatrix.sync.aligned.m8n8.x4.trans.shared.b16 {%0,%1,%2,%3}, [%4];" \
        : "=r"((R)[0]), "=r"((R)[1]), "=r"((R)[2]), "=r"((R)[3]) : "r"(addr))

#define MMA_F16(C, A, b0, b1)                                                  \
    asm volatile("mma.sync.aligned.m16n8k16.row.col.f32.f16.f16.f32 "          \
        "{%0,%1,%2,%3}, {%4,%5,%6,%7}, {%8,%9}, {%0,%1,%2,%3};"                \
        : "+f"((C)[0]), "+f"((C)[1]), "+f"((C)[2]), "+f"((C)[3])               \
        : "r"((A)[0]), "r"((A)[1]), "r"((A)[2]), "r"((A)[3]), "r"(b0), "r"(b1))

#define CP_ASYNC16(dst_u32, src_ptr)                                           \
    asm volatile("cp.async.cg.shared.global [%0], [%1], 16;"                   \
        :: "r"(dst_u32), "l"(src_ptr))
#define CP_COMMIT  asm volatile("cp.async.commit_group;")
#define CP_WAIT0   asm volatile("cp.async.wait_group 0;")

__global__ void __launch_bounds__(NTHREADS, 1)
pose_mlp_kernel(const float* __restrict__ pose,
                const float* __restrict__ ln1g, const float* __restrict__ ln1b,
                const float* __restrict__ w1,   const float* __restrict__ b1,
                const float* __restrict__ w2,   const float* __restrict__ b2,
                const float* __restrict__ ln2g, const float* __restrict__ ln2b,
                float* __restrict__ out, int ntiles)
{
    extern __shared__ char smem[];
    __half* W2h = (__half*)(smem + OFF_W2);
    __half* W1h = (__half*)(smem + OFF_W1);
    __half* A1h = (__half*)(smem + OFF_A1);
    __half* Hh  = (__half*)(smem + OFF_H);
    float*  ST  = (float*)(smem + OFF_ST);    // ST[2][5760]
    float2* PS  = (float2*)(smem + OFF_PS);
    float*  LNC = (float*)(smem + OFF_LNC);

    const int tid  = threadIdx.x;
    const int lane = tid & 31;
    const int warp = tid >> 5;
    const int g    = lane >> 2;
    const int t4   = lane & 3;
    const int wr   = warp >> 2;   // warp row (4)
    const int wc   = warp & 3;    // warp col (4)

    const int lm_m  = lane >> 3;
    const int lm_r  = lane & 7;
    const int a_row = lm_r + (lm_m & 1) * 8;
    const int a_kof = (lm_m >> 1) * 8;
    const int b_kof = lm_r + (lm_m & 1) * 8;
    const int b_cof = (lm_m >> 1) * 8;

    // LN1 decomposition: 4 threads per row
    const int ln_r = tid >> 2;
    const int ln_s = tid & 3;
    const int ln_c0 = ln_s * 12;

    // ---- one-time: weights -> smem as fp16 ----
    for (int i = tid; i < 8192; i += NTHREADS) {            // W2 via float4
        int k = i >> 6;
        int c = (i & 63) << 2;
        float4 v = reinterpret_cast<const float4*>(w2)[i];
        __half2* d = (__half2*)&W2h[k * SW2 + c];
        d[0] = __floats2half2_rn(v.x, v.y);
        d[1] = __floats2half2_rn(v.z, v.w);
    }
    for (int i = tid; i < 48 * 128; i += NTHREADS) {        // W1, rows 45..47 zero
        int k = i >> 7;
        int c = i & 127;
        W1h[k * SW1 + c] = (k < 45) ? __float2half_rn(w1[k * 128 + c])
                                    : __float2half_rn(0.0f);
    }
    if (tid < 45) { LNC[tid] = ln1g[tid]; LNC[48 + tid] = ln1b[tid]; }

    // ---- prologue: stage + LN1 for first tile ----
    int tile = blockIdx.x;
    if (tile < ntiles) {
        const float4* s4 = (const float4*)(pose + (size_t)tile * 5760);
        unsigned dst = su32(ST);
        #pragma unroll
        for (int it = 0; it < 3; it++) {
            int i = tid + it * NTHREADS;
            if (i < 1440) CP_ASYNC16(dst + i * 16, s4 + i);
        }
        CP_COMMIT; CP_WAIT0;
    }
    __syncthreads();
    // LN1 (4 threads/row) -> A1h
    {
        const float* row = &ST[ln_r * 45];
        float x[12]; float s = 0.f, q = 0.f;
        #pragma unroll
        for (int j = 0; j < 12; j++) {
            int c = ln_c0 + j;
            x[j] = (c < 45) ? row[c] : 0.f;
            s += x[j]; q += x[j] * x[j];
        }
        s += __shfl_xor_sync(0xffffffffu, s, 1); q += __shfl_xor_sync(0xffffffffu, q, 1);
        s += __shfl_xor_sync(0xffffffffu, s, 2); q += __shfl_xor_sync(0xffffffffu, q, 2);
        float mu   = s * (1.0f / 45.0f);
        float var  = q * (1.0f / 45.0f) - mu * mu;
        float rstd = rsqrtf(fmaxf(var, 0.f) + 1e-5f);
        __half2* dstp = (__half2*)&A1h[ln_r * SA + ln_c0];
        #pragma unroll
        for (int j2 = 0; j2 < 6; j2++) {
            int c = ln_c0 + 2 * j2;
            float y0 = (c     < 45) ? (x[2*j2]   - mu) * rstd * LNC[c]     + LNC[48 + c]     : 0.f;
            float y1 = (c + 1 < 45) ? (x[2*j2+1] - mu) * rstd * LNC[c + 1] + LNC[48 + c + 1] : 0.f;
            dstp[j2] = __floats2half2_rn(y0, y1);
        }
    }

    int p = 1;
    for (; tile < ntiles; tile += gridDim.x, p ^= 1) {
        const int tn = tile + gridDim.x;
        // ---- prefetch next tile into ST[p] (completes under GEMM2) ----
        if (tn < ntiles) {
            const float4* s4 = (const float4*)(pose + (size_t)tn * 5760);
            unsigned dst = su32(ST) + p * 23040;
            #pragma unroll
            for (int it = 0; it < 3; it++) {
                int i = tid + it * NTHREADS;
                if (i < 1440) CP_ASYNC16(dst + i * 16, s4 + i);
            }
        }
        CP_COMMIT;
        __syncthreads();   // A1h ready; Hh free

        // ---- GEMM1: [128x48] x [48x128] (bias folded) ----
        float acc1[2][4][4];
        #pragma unroll
        for (int n = 0; n < 4; n++) {
            float2 bv = *reinterpret_cast<const float2*>(&b1[wc * 32 + n * 8 + 2 * t4]);
            #pragma unroll
            for (int mi = 0; mi < 2; mi++) {
                acc1[mi][n][0] = bv.x; acc1[mi][n][1] = bv.y;
                acc1[mi][n][2] = bv.x; acc1[mi][n][3] = bv.y;
            }
        }
        {
            unsigned ab = su32(A1h) + ((wr * 32 + a_row) * SA + a_kof) * 2;
            unsigned bb = su32(W1h) + (b_kof * SW1 + wc * 32 + b_cof) * 2;
            #pragma unroll
            for (int kk = 0; kk < 3; kk++) {
                unsigned a[2][4], b[2][4];
                LDM_X4(a[0], ab + (kk * 16) * 2);
                LDM_X4(a[1], ab + (16 * SA + kk * 16) * 2);
                LDM_X4T(b[0], bb + (kk * 16 * SW1) * 2);
                LDM_X4T(b[1], bb + (kk * 16 * SW1 + 16) * 2);
                #pragma unroll
                for (int n = 0; n < 4; n++) {
                    int pp = n >> 1, qf = (n & 1) * 2;
                    MMA_F16(acc1[0][n], a[0], b[pp][qf], b[pp][qf + 1]);
                    MMA_F16(acc1[1][n], a[1], b[pp][qf], b[pp][qf + 1]);
                }
            }
        }

        // ---- epilogue1: exact GELU -> fp16 H ----
        #pragma unroll
        for (int mi = 0; mi < 2; mi++) {
            int r = wr * 32 + mi * 16 + g;
            #pragma unroll
            for (int n = 0; n < 4; n++) {
                int c = wc * 32 + n * 8 + 2 * t4;
                *(__half2*)&Hh[r * SHH + c] =
                    __floats2half2_rn(gelu_exact(acc1[mi][n][0]), gelu_exact(acc1[mi][n][1]));
                *(__half2*)&Hh[(r + 8) * SHH + c] =
                    __floats2half2_rn(gelu_exact(acc1[mi][n][2]), gelu_exact(acc1[mi][n][3]));
            }
        }
        __syncthreads();   // Hh ready

        // ---- GEMM2: [128x128] x [128x256] (bias folded) ----
        float acc2[2][8][4];
        #pragma unroll
        for (int n = 0; n < 8; n++) {
            float2 bv = *reinterpret_cast<const float2*>(&b2[wc * 64 + n * 8 + 2 * t4]);
            #pragma unroll
            for (int mi = 0; mi < 2; mi++) {
                acc2[mi][n][0] = bv.x; acc2[mi][n][1] = bv.y;
                acc2[mi][n][2] = bv.x; acc2[mi][n][3] = bv.y;
            }
        }
        {
            unsigned ab = su32(Hh)  + ((wr * 32 + a_row) * SHH + a_kof) * 2;
            unsigned bb = su32(W2h) + (b_kof * SW2 + wc * 64 + b_cof) * 2;
            #pragma unroll 2
            for (int kk = 0; kk < 8; kk++) {
                unsigned a[2][4], b[4][4];
                LDM_X4(a[0], ab + (kk * 16) * 2);
                LDM_X4(a[1], ab + (16 * SHH + kk * 16) * 2);
                #pragma unroll
                for (int pp = 0; pp < 4; pp++)
                    LDM_X4T(b[pp], bb + (kk * 16 * SW2 + pp * 16) * 2);
                #pragma unroll
                for (int n = 0; n < 8; n++) {
                    int pp = n >> 1, qf = (n & 1) * 2;
                    MMA_F16(acc2[0][n], a[0], b[pp][qf], b[pp][qf + 1]);
                    MMA_F16(acc2[1][n], a[1], b[pp][qf], b[pp][qf + 1]);
                }
            }
        }

        // ---- LN2 partial sums ----
        #pragma unroll
        for (int mi = 0; mi < 2; mi++) {
            float s0 = 0.f, q0 = 0.f, s1 = 0.f, q1 = 0.f;
            #pragma unroll
            for (int n = 0; n < 8; n++) {
                float a0 = acc2[mi][n][0], a1 = acc2[mi][n][1];
                float a2 = acc2[mi][n][2], a3 = acc2[mi][n][3];
                s0 += a0 + a1; q0 += a0 * a0 + a1 * a1;
                s1 += a2 + a3; q1 += a2 * a2 + a3 * a3;
            }
            #pragma unroll
            for (int off = 1; off <= 2; off <<= 1) {
                s0 += __shfl_xor_sync(0xffffffffu, s0, off);
                q0 += __shfl_xor_sync(0xffffffffu, q0, off);
                s1 += __shfl_xor_sync(0xffffffffu, s1, off);
                q1 += __shfl_xor_sync(0xffffffffu, q1, off);
            }
            if (t4 == 0) {
                int r = wr * 32 + mi * 16 + g;
                PS[r * 4 + wc]       = make_float2(s0, q0);
                PS[(r + 8) * 4 + wc] = make_float2(s1, q1);
            }
        }
        CP_WAIT0;          // next tile's stage complete (cheap: overlapped by GEMM2)
        __syncthreads();   // PS ready + all threads' cp.async done

        // ---- epilogue2 stores (STG fire-and-forget) ----
        float* outp = out + (size_t)tile * TILE_M * 256;
        #pragma unroll
        for (int mi = 0; mi < 2; mi++) {
            #pragma unroll
            for (int h = 0; h < 2; h++) {
                int r = wr * 32 + mi * 16 + g + h * 8;
                float2 p0 = PS[r * 4 + 0], p1 = PS[r * 4 + 1];
                float2 p2 = PS[r * 4 + 2], p3 = PS[r * 4 + 3];
                float s = p0.x + p1.x + p2.x + p3.x;
                float q = p0.y + p1.y + p2.y + p3.y;
                float mu   = s * (1.0f / 256.0f);
                float var  = q * (1.0f / 256.0f) - mu * mu;
                float rstd = rsqrtf(fmaxf(var, 0.f) + 1e-5f);
                #pragma unroll
                for (int n = 0; n < 8; n++) {
                    int c = wc * 64 + n * 8 + 2 * t4;
                    float2 gv = *reinterpret_cast<const float2*>(&ln2g[c]);
                    float2 bv = *reinterpret_cast<const float2*>(&ln2b[c]);
                    float v0 = acc2[mi][n][h * 2 + 0];
                    float v1 = acc2[mi][n][h * 2 + 1];
                    float2 o;
                    o.x = (v0 - mu) * rstd * gv.x + bv.x;
                    o.y = (v1 - mu) * rstd * gv.y + bv.y;
                    *reinterpret_cast<float2*>(&outp[(size_t)r * 256 + c]) = o;
                }
            }
        }

        // ---- LN1 for next tile (overlaps the STGs above) ----
        if (tn < ntiles) {
            const float* row = &ST[p * 5760 + ln_r * 45];
            float x[12]; float s = 0.f, q = 0.f;
            #pragma unroll
            for (int j = 0; j < 12; j++) {
                int c = ln_c0 + j;
                x[j] = (c < 45) ? row[c] : 0.f;
                s += x[j]; q += x[j] * x[j];
            }
            s += __shfl_xor_sync(0xffffffffu, s, 1); q += __shfl_xor_sync(0xffffffffu, q, 1);
            s += __shfl_xor_sync(0xffffffffu, s, 2); q += __shfl_xor_sync(0xffffffffu, q, 2);
            float mu   = s * (1.0f / 45.0f);
            float var  = q * (1.0f / 45.0f) - mu * mu;
            float rstd = rsqrtf(fmaxf(var, 0.f) + 1e-5f);
            __half2* dstp = (__half2*)&A1h[ln_r * SA + ln_c0];
            #pragma unroll
            for (int j2 = 0; j2 < 6; j2++) {
                int c = ln_c0 + 2 * j2;
                float y0 = (c     < 45) ? (x[2*j2]   - mu) * rstd * LNC[c]     + LNC[48 + c]     : 0.f;
                float y1 = (c + 1 < 45) ? (x[2*j2+1] - mu) * rstd * LNC[c + 1] + LNC[48 + c + 1] : 0.f;
                dstp[j2] = __floats2half2_rn(y0, y1);
            }
        }
    }
}

extern "C" void kernel_launch(void* const* d_in, const int* in_sizes, int n_in,
                              void* d_out, int out_size)
{
    const float* pose = (const float*)d_in[0];
    const float* ln1g = (const float*)d_in[1];
    const float* ln1b = (const float*)d_in[2];
    const float* w1   = (const float*)d_in[3];
    const float* b1   = (const float*)d_in[4];
    const float* w2   = (const float*)d_in[5];
    const float* b2   = (const float*)d_in[6];
    const float* ln2g = (const float*)d_in[7];
    const float* ln2b = (const float*)d_in[8];
    float* out = (float*)d_out;

    int nrows  = in_sizes[0] / 45;
    int ntiles = nrows / TILE_M;

    int dev = 0;
    cudaGetDevice(&dev);
    int nsm = 148;
    cudaDeviceGetAttribute(&nsm, cudaDevAttrMultiProcessorCount, dev);

    cudaFuncSetAttribute(pose_mlp_kernel,
                         cudaFuncAttributeMaxDynamicSharedMemorySize, SMEM_BYTES);

    int grid = nsm < ntiles ? nsm : ntiles;
    pose_mlp_kernel<<<grid, NTHREADS, SMEM_BYTES>>>(
        pose, ln1g, ln1b, w1, b1, w2, b2, ln2g, ln2b, out, ntiles);
}